// round 3
// baseline (speedup 1.0000x reference)
#include <cuda_runtime.h>
#include <math.h>

// ---------------- problem constants ----------------
#define BATCH   8
#define SEQ     4096
#define MTOT    (BATCH*SEQ)      // 32768
#define DM      128              // d_model
#define DI      256              // d_inner
#define DS      16               // d_state
#define DR      8                // dt_rank
#define DXP     (DR + 2*DS)      // 40
#define DFF     512
#define VOCABSZ 4096
#define NL      4

// ---------------- device scratch (no allocations allowed) ----------------
__device__ float g_X  [MTOT*DM];       // 16 MB
__device__ float g_XN [MTOT*DM];       // 16 MB
__device__ float g_XZ [MTOT*2*DI];     // 64 MB
__device__ float g_U  [MTOT*DI];       // 32 MB
__device__ float g_DBC[MTOT*DXP];      //  5 MB
__device__ float g_DT [MTOT*DI];       // 32 MB
__device__ float g_Y  [MTOT*DI];       // 32 MB
__device__ float g_H  [MTOT*DFF];      // 64 MB

// ---------------- embedding gather ----------------
__global__ void embed_kernel(const int* __restrict__ tokens,
                             const float* __restrict__ emb) {
    int idx = blockIdx.x * blockDim.x + threadIdx.x;   // over MTOT * DM/4
    int m   = idx >> 5;            // DM/4 = 32 float4 per row
    int c4  = idx & 31;
    int t   = tokens[m];
    ((float4*)g_X)[(size_t)m*32 + c4] = ((const float4*)emb)[(size_t)t*32 + c4];
}

// ---------------- layernorm: one warp per row of 128 ----------------
__global__ void ln_kernel(const float* __restrict__ w, const float* __restrict__ b) {
    int gw   = (blockIdx.x * blockDim.x + threadIdx.x) >> 5;
    int lane = threadIdx.x & 31;
    float4 v = ((const float4*)g_X)[(size_t)gw*32 + lane];
    float s = v.x + v.y + v.z + v.w;
    #pragma unroll
    for (int o = 16; o; o >>= 1) s += __shfl_xor_sync(0xffffffffu, s, o);
    float mu = s * (1.0f/DM);
    float dx = v.x-mu, dy = v.y-mu, dz = v.z-mu, dw = v.w-mu;
    float q = dx*dx + dy*dy + dz*dz + dw*dw;
    #pragma unroll
    for (int o = 16; o; o >>= 1) q += __shfl_xor_sync(0xffffffffu, q, o);
    float rstd = rsqrtf(q * (1.0f/DM) + 1e-5f);
    float4 w4 = ((const float4*)w)[lane];
    float4 b4 = ((const float4*)b)[lane];
    float4 o4;
    o4.x = dx*rstd*w4.x + b4.x;
    o4.y = dy*rstd*w4.y + b4.y;
    o4.z = dz*rstd*w4.z + b4.z;
    o4.w = dw*rstd*w4.w + b4.w;
    ((float4*)g_XN)[(size_t)gw*32 + lane] = o4;
}

// ---------------- tiled fp32 GEMM: C[M,N] = A[M,K] @ B[K,N] (+bias)(relu) ----
// BM=128 BN=128 BK=16 TM=8 TN=8, 256 threads. Requires M%128==0, N%128==0, K%16==0.
template<bool BIAS, bool RELU>
__global__ __launch_bounds__(256) void sgemm_kernel(
    int M, int N, int K,
    const float* __restrict__ A, const float* __restrict__ B,
    const float* __restrict__ bias, float* __restrict__ C)
{
    constexpr int BM = 128, BN = 128, BK = 16, TM = 8, TN = 8;
    __shared__ __align__(16) float As[BK][BM];
    __shared__ __align__(16) float Bs[BK][BN];
    const int tid  = threadIdx.x;
    const int bx   = blockIdx.x, by = blockIdx.y;
    const int tcol = tid & 15;     // BN/TN = 16
    const int trow = tid >> 4;     // BM/TM = 16
    const float* Ab = A + (size_t)by * BM * K;
    const float* Bb = B + (size_t)bx * BN;
    float*       Cb = C + (size_t)by * BM * N + (size_t)bx * BN;

    const int aCol  = tid & 3;     // BK/4 = 4 float4 per A row
    const int aRow0 = tid >> 2;    // 0..63
    const int bCol  = tid & 31;    // BN/4 = 32 float4 per B row
    const int bRow0 = tid >> 5;    // 0..7

    float acc[TM][TN];
    #pragma unroll
    for (int i = 0; i < TM; i++)
        #pragma unroll
        for (int j = 0; j < TN; j++) acc[i][j] = 0.f;

    for (int k0 = 0; k0 < K; k0 += BK) {
        #pragma unroll
        for (int r = 0; r < BM; r += 64) {
            float4 v = *(const float4*)&Ab[(size_t)(aRow0 + r)*K + k0 + aCol*4];
            As[aCol*4+0][aRow0+r] = v.x;
            As[aCol*4+1][aRow0+r] = v.y;
            As[aCol*4+2][aRow0+r] = v.z;
            As[aCol*4+3][aRow0+r] = v.w;
        }
        #pragma unroll
        for (int r = 0; r < BK; r += 8) {
            *(float4*)&Bs[bRow0+r][bCol*4] =
                *(const float4*)&Bb[(size_t)(k0 + bRow0 + r)*N + bCol*4];
        }
        __syncthreads();
        #pragma unroll
        for (int k = 0; k < BK; k++) {
            float4 a0 = *(const float4*)&As[k][trow*TM];
            float4 a1 = *(const float4*)&As[k][trow*TM+4];
            float4 b0 = *(const float4*)&Bs[k][tcol*TN];
            float4 b1 = *(const float4*)&Bs[k][tcol*TN+4];
            float ra[8] = {a0.x,a0.y,a0.z,a0.w,a1.x,a1.y,a1.z,a1.w};
            float rb[8] = {b0.x,b0.y,b0.z,b0.w,b1.x,b1.y,b1.z,b1.w};
            #pragma unroll
            for (int i = 0; i < TM; i++)
                #pragma unroll
                for (int j = 0; j < TN; j++)
                    acc[i][j] += ra[i] * rb[j];
        }
        __syncthreads();
    }
    float bv[TN];
    if (BIAS) {
        #pragma unroll
        for (int j = 0; j < TN; j++) bv[j] = bias[(size_t)bx*BN + tcol*TN + j];
    }
    #pragma unroll
    for (int i = 0; i < TM; i++) {
        #pragma unroll
        for (int j = 0; j < TN; j += 4) {
            float4 o;
            o.x = acc[i][j+0]; o.y = acc[i][j+1]; o.z = acc[i][j+2]; o.w = acc[i][j+3];
            if (BIAS) { o.x += bv[j+0]; o.y += bv[j+1]; o.z += bv[j+2]; o.w += bv[j+3]; }
            if (RELU) { o.x = fmaxf(o.x,0.f); o.y = fmaxf(o.y,0.f);
                        o.z = fmaxf(o.z,0.f); o.w = fmaxf(o.w,0.f); }
            *(float4*)&Cb[(size_t)(trow*TM+i)*N + tcol*TN + j] = o;
        }
    }
}

// ---------------- depthwise causal conv(4) + SiLU ----------------
// xc = XZ[..., :DI]; u = silu(conv(xc) + conv_b)
__global__ void conv_silu_kernel(const float* __restrict__ cw,
                                 const float* __restrict__ cb) {
    int m = blockIdx.x;           // token index (b*SEQ + l)
    int d = threadIdx.x;          // channel
    int l = m & (SEQ - 1);
    float4 w4 = ((const float4*)cw)[d];   // cw[d][0..3]
    const float* xc = g_XZ + (size_t)m * (2*DI) + d;
    float acc = cb[d] + w4.w * xc[0];
    if (l >= 1) acc += w4.z * xc[-(2*DI)];
    if (l >= 2) acc += w4.y * xc[-2*(2*DI)];
    if (l >= 3) acc += w4.x * xc[-3*(2*DI)];
    g_U[(size_t)m*DI + d] = acc * (1.0f / (1.0f + __expf(-acc)));   // silu
}

// ---------------- x-projection: DBC[M,40] = U[M,256] @ Wxp[256,40] ----------
__global__ __launch_bounds__(256) void xproj_kernel(const float* __restrict__ W) {
    __shared__ float Ws[DI*DXP];           // 40 KB
    for (int i = threadIdx.x; i < DI*DXP; i += blockDim.x) Ws[i] = W[i];
    __syncthreads();
    int warp = threadIdx.x >> 5, lane = threadIdx.x & 31;
    int m0 = blockIdx.x * 32;
    for (int p = 0; p < 4; p++) {
        int m = m0 + p*8 + warp;
        const float* u = g_U + (size_t)m * DI;
        float acc0 = 0.f, acc1 = 0.f;
        for (int k0 = 0; k0 < DI; k0 += 32) {
            float uval = u[k0 + lane];
            #pragma unroll
            for (int j = 0; j < 32; j++) {
                float uv = __shfl_sync(0xffffffffu, uval, j);
                acc0 += uv * Ws[(k0+j)*DXP + lane];
                if (lane < 8) acc1 += uv * Ws[(k0+j)*DXP + 32 + lane];
            }
        }
        g_DBC[(size_t)m*DXP + lane] = acc0;
        if (lane < 8) g_DBC[(size_t)m*DXP + 32 + lane] = acc1;
    }
}

// ---------------- dt = softplus(DBC[:, :8] @ Wdt[8,256] + b_dt) -------------
__global__ __launch_bounds__(256) void dt_kernel(const float* __restrict__ Wdt,
                                                 const float* __restrict__ bdt) {
    __shared__ float Ws[DR*DI];
    for (int i = threadIdx.x; i < DR*DI; i += 256) Ws[i] = Wdt[i];
    __syncthreads();
    int d  = threadIdx.x;
    float bv = bdt[d];
    int m0 = blockIdx.x * 16;
    for (int p = 0; p < 16; p++) {
        int m = m0 + p;
        const float* r = g_DBC + (size_t)m * DXP;
        float acc = bv;
        #pragma unroll
        for (int j = 0; j < DR; j++) acc += r[j] * Ws[j*DI + d];
        g_DT[(size_t)m*DI + d] = (acc > 20.f) ? acc : log1pf(__expf(acc));
    }
}

// ---------------- selective scan: lane-per-state, 2 channels per warp -------
// h[s] = exp(dt*A[s])*h[s] + dt*u*B[s];  y = sum_s h[s]*C[s]
// then y = (y + u*D)*silu(z)
__global__ __launch_bounds__(256) void scan_kernel(const float* __restrict__ A_log,
                                                   const float* __restrict__ D_skip) {
    int warp = threadIdx.x >> 5;
    int lane = threadIdx.x & 31;
    int half = lane >> 4;
    int s    = lane & 15;
    int ch   = blockIdx.x * 16 + warp * 2 + half;   // 0..2047
    int b    = ch >> 8;
    int d    = ch & 255;
    float a   = -__expf(A_log[d*DS + s]);
    float dsk = D_skip[d];
    float h   = 0.f;
    size_t m  = (size_t)b * SEQ;
    for (int l = 0; l < SEQ; l++, m++) {
        float dtv = g_DT[m*DI + d];
        float uv  = g_U [m*DI + d];
        float Bv  = g_DBC[m*DXP + DR + s];
        float Cv  = g_DBC[m*DXP + DR + DS + s];
        h = __expf(dtv * a) * h + dtv * uv * Bv;
        float y = h * Cv;
        y += __shfl_xor_sync(0xffffffffu, y, 8);
        y += __shfl_xor_sync(0xffffffffu, y, 4);
        y += __shfl_xor_sync(0xffffffffu, y, 2);
        y += __shfl_xor_sync(0xffffffffu, y, 1);
        if (s == 0) {
            float zv = g_XZ[m*(2*DI) + DI + d];
            g_Y[m*DI + d] = (y + uv * dsk) * (zv / (1.0f + __expf(-zv)));
        }
    }
}

// ---------------- host launch ----------------
extern "C" void kernel_launch(void* const* d_in, const int* in_sizes, int n_in,
                              void* d_out, int out_size) {
    const int*   tokens  = (const int*)  d_in[0];
    const float* emb     = (const float*)d_in[1];
    const float* ln_w    = (const float*)d_in[2];
    const float* ln_b    = (const float*)d_in[3];
    const float* W_in    = (const float*)d_in[4];
    const float* conv_w  = (const float*)d_in[5];
    const float* conv_b  = (const float*)d_in[6];
    const float* W_xproj = (const float*)d_in[7];
    const float* W_dt    = (const float*)d_in[8];
    const float* b_dt    = (const float*)d_in[9];
    const float* A_log   = (const float*)d_in[10];
    const float* D_skip  = (const float*)d_in[11];
    const float* W_out   = (const float*)d_in[12];
    const float* W1      = (const float*)d_in[13];
    const float* b1      = (const float*)d_in[14];
    const float* W2      = (const float*)d_in[15];
    const float* b2      = (const float*)d_in[16];
    float* out = (float*)d_out;

    float *X, *XN, *XZ, *U, *DBC, *DT, *Y, *H;
    cudaGetSymbolAddress((void**)&X,   g_X);
    cudaGetSymbolAddress((void**)&XN,  g_XN);
    cudaGetSymbolAddress((void**)&XZ,  g_XZ);
    cudaGetSymbolAddress((void**)&U,   g_U);
    cudaGetSymbolAddress((void**)&DBC, g_DBC);
    cudaGetSymbolAddress((void**)&DT,  g_DT);
    cudaGetSymbolAddress((void**)&Y,   g_Y);
    cudaGetSymbolAddress((void**)&H,   g_H);

    // embedding
    embed_kernel<<<MTOT*32/256, 256>>>(tokens, emb);

    for (int layer = 0; layer < NL; layer++) {
        // layernorm (8 rows per 256-thread block)
        ln_kernel<<<MTOT/8, 256>>>(ln_w + layer*DM, ln_b + layer*DM);
        // xz = xn @ W_in   [32768,128]x[128,512]
        sgemm_kernel<false,false><<<dim3(2*DI/128, MTOT/128), 256>>>(
            MTOT, 2*DI, DM, XN, W_in + (size_t)layer*DM*2*DI, nullptr, XZ);
        // depthwise conv + silu
        conv_silu_kernel<<<MTOT, DI>>>(conv_w + (size_t)layer*DI*4,
                                       conv_b + (size_t)layer*DI);
        // dbc = u @ W_xproj  [32768,256]x[256,40]
        xproj_kernel<<<MTOT/32, 256>>>(W_xproj + (size_t)layer*DI*DXP);
        // dt = softplus(dbc[:, :8] @ W_dt + b_dt)
        dt_kernel<<<MTOT/16, 256>>>(W_dt + (size_t)layer*DR*DI,
                                    b_dt + (size_t)layer*DI);
        // selective scan + gating
        scan_kernel<<<BATCH*DI/16, 256>>>(A_log  + (size_t)layer*DI*DS,
                                          D_skip + (size_t)layer*DI);
        // x = y @ W_out   [32768,256]x[256,128]
        sgemm_kernel<false,false><<<dim3(DM/128, MTOT/128), 256>>>(
            MTOT, DM, DI, Y, W_out + (size_t)layer*DI*DM, nullptr, X);
    }

    // h = relu(x @ W1 + b1)   [32768,128]x[128,512]
    sgemm_kernel<true,true><<<dim3(DFF/128, MTOT/128), 256>>>(
        MTOT, DFF, DM, X, W1, b1, H);
    // out = h @ W2 + b2       [32768,512]x[512,4096]
    sgemm_kernel<true,false><<<dim3(VOCABSZ/128, MTOT/128), 256>>>(
        MTOT, VOCABSZ, DFF, H, W2, b2, out);
}

// round 7
// speedup vs baseline: 1.0482x; 1.0482x over previous
#include <cuda_runtime.h>
#include <cuda_bf16.h>
#include <stdint.h>
#include <math.h>

// ---------------- problem constants ----------------
#define BATCH   8
#define SEQ     4096
#define MTOT    (BATCH*SEQ)      // 32768
#define DM      128              // d_model
#define DI      256              // d_inner
#define DS      16               // d_state
#define DR      8                // dt_rank
#define DXPP    64               // padded xproj out (real 40)
#define DFF     512
#define VOCABSZ 4096
#define NL      4

// ---------------- device scratch (no allocations allowed) ----------------
__device__ __align__(16) float g_X  [MTOT*DM];        // 16 MB
__device__ __align__(16) float g_XZ [MTOT*2*DI];      // 64 MB
__device__ __align__(16) float g_U  [MTOT*DI];        // 32 MB
__device__ __align__(16) float g_DBC[MTOT*DXPP];      //  8 MB
__device__ __align__(16) float g_DT [MTOT*DI];        // 32 MB
__device__ __align__(16) float g_H  [MTOT*DFF];       // 64 MB
__device__ __align__(16) __nv_bfloat16 g_Acat[(size_t)MTOT*1536];   // 96 MB
__device__ __align__(16) __nv_bfloat16 g_Bcat[(size_t)VOCABSZ*1536];// 12 MB

// ---------------- helpers ----------------
__device__ __forceinline__ uint32_t smem_u32(const void* p) {
    uint32_t a;
    asm("{ .reg .u64 t; cvta.to.shared.u64 t, %1; cvt.u32.u64 %0, t; }" : "=r"(a) : "l"(p));
    return a;
}
__device__ __forceinline__ void cp16(uint32_t dst, const void* src) {
    asm volatile("cp.async.cg.shared.global [%0], [%1], 16;" :: "r"(dst), "l"(src));
}
__device__ __forceinline__ void cp_commit() {
    asm volatile("cp.async.commit_group;" ::: "memory");
}
__device__ __forceinline__ void cp_wait0() {
    asm volatile("cp.async.wait_group 0;" ::: "memory");
}
__device__ __forceinline__ void ldsm_x4(uint32_t& r0, uint32_t& r1, uint32_t& r2,
                                        uint32_t& r3, uint32_t addr) {
    asm volatile("ldmatrix.sync.aligned.m8n8.x4.shared.b16 {%0,%1,%2,%3}, [%4];"
                 : "=r"(r0), "=r"(r1), "=r"(r2), "=r"(r3) : "r"(addr));
}
__device__ __forceinline__ void mma16816(float* c, const uint32_t* a, const uint32_t* b) {
    asm volatile("mma.sync.aligned.m16n8k16.row.col.f32.bf16.bf16.f32 "
                 "{%0,%1,%2,%3},{%4,%5,%6,%7},{%8,%9},{%0,%1,%2,%3};"
                 : "+f"(c[0]), "+f"(c[1]), "+f"(c[2]), "+f"(c[3])
                 : "r"(a[0]), "r"(a[1]), "r"(a[2]), "r"(a[3]), "r"(b[0]), "r"(b[1]));
}
__device__ __forceinline__ void split_bf(float x, unsigned short& h, unsigned short& l) {
    __nv_bfloat16 hb = __float2bfloat16(x);
    __nv_bfloat16 lb = __float2bfloat16(x - __bfloat162float(hb));
    h = __bfloat16_as_ushort(hb);
    l = __bfloat16_as_ushort(lb);
}

// ---------------- embedding gather ----------------
__global__ void embed_kernel(const int* __restrict__ tokens,
                             const float* __restrict__ emb) {
    int idx = blockIdx.x * blockDim.x + threadIdx.x;
    int m = idx >> 5, c4 = idx & 31;
    int t = tokens[m];
    ((float4*)g_X)[(size_t)m*32 + c4] = ((const float4*)emb)[(size_t)t*32 + c4];
}

// ---------------- layernorm fused with hi/lo bf16 cat: out [M, 384] ----------
__global__ void ln_cvt_kernel(const float* __restrict__ w, const float* __restrict__ b,
                              const float* __restrict__ X, __nv_bfloat16* __restrict__ out) {
    int gw   = (blockIdx.x * blockDim.x + threadIdx.x) >> 5;
    int lane = threadIdx.x & 31;
    float4 v = ((const float4*)X)[(size_t)gw*32 + lane];
    float s = v.x + v.y + v.z + v.w;
    #pragma unroll
    for (int o = 16; o; o >>= 1) s += __shfl_xor_sync(0xffffffffu, s, o);
    float mu = s * (1.0f/DM);
    float dx = v.x-mu, dy = v.y-mu, dz = v.z-mu, dw = v.w-mu;
    float q = dx*dx + dy*dy + dz*dz + dw*dw;
    #pragma unroll
    for (int o = 16; o; o >>= 1) q += __shfl_xor_sync(0xffffffffu, q, o);
    float rstd = rsqrtf(q * (1.0f/DM) + 1e-5f);
    float4 w4 = ((const float4*)w)[lane];
    float4 b4 = ((const float4*)b)[lane];
    float o0 = dx*rstd*w4.x + b4.x;
    float o1 = dy*rstd*w4.y + b4.y;
    float o2 = dz*rstd*w4.z + b4.z;
    float o3 = dw*rstd*w4.w + b4.w;
    unsigned short h0,h1,h2,h3,l0,l1,l2,l3;
    split_bf(o0,h0,l0); split_bf(o1,h1,l1); split_bf(o2,h2,l2); split_bf(o3,h3,l3);
    uint32_t ph0 = h0 | ((uint32_t)h1<<16), ph1 = h2 | ((uint32_t)h3<<16);
    uint32_t pl0 = l0 | ((uint32_t)l1<<16), pl1 = l2 | ((uint32_t)l3<<16);
    uint32_t* ob = (uint32_t*)(out + (size_t)gw*384);
    ob[lane*2]       = ph0; ob[lane*2+1]       = ph1;   // hi  [0,128)
    ob[64 + lane*2]  = pl0; ob[64 + lane*2+1]  = pl1;   // lo  [128,256)
    ob[128 + lane*2] = ph0; ob[128 + lane*2+1] = ph1;   // hi  [256,384)
}

// ---------------- generic activation hi/lo cat: in [M,K] fp32 -> out [M,3K] --
__global__ void cvtA_kernel(const float* __restrict__ in, __nv_bfloat16* __restrict__ out,
                            int K) {
    int i4 = blockIdx.x * blockDim.x + threadIdx.x;
    int kq = K >> 2;
    int m  = i4 / kq;
    int k  = (i4 - m*kq) << 2;
    float4 v = ((const float4*)in)[i4];
    unsigned short h0,h1,h2,h3,l0,l1,l2,l3;
    split_bf(v.x,h0,l0); split_bf(v.y,h1,l1); split_bf(v.z,h2,l2); split_bf(v.w,h3,l3);
    uint32_t ph0 = h0 | ((uint32_t)h1<<16), ph1 = h2 | ((uint32_t)h3<<16);
    uint32_t pl0 = l0 | ((uint32_t)l1<<16), pl1 = l2 | ((uint32_t)l3<<16);
    uint32_t* o = (uint32_t*)(out + (size_t)m*3*K);
    int ki = k >> 1;
    o[ki] = ph0;              o[ki+1] = ph1;
    o[(K>>1)+ki] = pl0;       o[(K>>1)+ki+1] = pl1;
    o[K+ki] = ph0;            o[K+ki+1] = ph1;
}

// ------------- weight transpose + hi/lo cat: W [K,N] fp32 -> out [Npad,3K] ---
// pairing: B = [hi | hi | lo]  (A = [hi | lo | hi])
__global__ void cvtB_kernel(const float* __restrict__ W, __nv_bfloat16* __restrict__ out,
                            int K, int N, int Npad) {
    int idx = blockIdx.x * blockDim.x + threadIdx.x;   // over Npad*K
    int n = idx / K, k = idx - n*K;
    float v = (n < N) ? W[(size_t)k*N + n] : 0.f;
    unsigned short h, l;
    split_bf(v, h, l);
    __nv_bfloat16* o = out + (size_t)n*3*K;
    o[k]       = __ushort_as_bfloat16(h);
    o[K + k]   = __ushort_as_bfloat16(h);
    o[2*K + k] = __ushort_as_bfloat16(l);
}

// ---------------- HMMA bf16 GEMM: D[m,n] = sum_k A[m,k]*B[n,k] ---------------
// A [M,Kc] bf16 row-major, B [Npad,Kc] bf16 row-major. 128x128 block, BK=32,
// 8 warps (2x4), warp tile 64x32, mma.sync m16n8k16, cp.async double buffer.
template<int NSTORE, bool BIAS, bool RELU>
__global__ __launch_bounds__(256, 2) void mma_gemm_kernel(
    int Kc, const __nv_bfloat16* __restrict__ A, const __nv_bfloat16* __restrict__ B,
    const float* __restrict__ bias, float* __restrict__ C, int ldc)
{
    constexpr int BM = 128, BN = 128, LDA = 40;   // 32 + 8 pad halves (80B row)
    __shared__ __align__(16) __nv_bfloat16 As[2][BM*LDA];
    __shared__ __align__(16) __nv_bfloat16 Bs[2][BN*LDA];
    const int tid = threadIdx.x, wid = tid >> 5, lane = tid & 31;
    const int warpM = wid >> 2, warpN = wid & 3;

    const __nv_bfloat16* Ag = A + (size_t)blockIdx.y * BM * Kc;
    const __nv_bfloat16* Bg = B + (size_t)blockIdx.x * BN * Kc;
    const uint32_t asb = smem_u32(As);
    const uint32_t bsb = smem_u32(Bs);

    const int ldRow = tid >> 2, ldSeg = tid & 3;    // 2 iters cover 128 rows x 4 segs

    float acc[4][4][4];
    #pragma unroll
    for (int i = 0; i < 4; i++)
        #pragma unroll
        for (int j = 0; j < 4; j++)
            #pragma unroll
            for (int q = 0; q < 4; q++) acc[i][j][q] = 0.f;

    // ldmatrix lane addressing (half-element offsets within a buffer)
    const int aRow  = warpM*64 + (lane & 15);
    const int aColH = (lane >> 4) * 8;
    const int bRow  = warpN*32 + (lane & 7) + ((lane >> 4) & 1) * 8;
    const int bColH = ((lane >> 3) & 1) * 8;

    auto load_tiles = [&](int buf, int k0) {
        #pragma unroll
        for (int i = 0; i < 2; i++) {
            int row = ldRow + i*64;
            uint32_t so = (uint32_t)((buf*BM*LDA + row*LDA + ldSeg*8) * 2);
            const __nv_bfloat16* as = Ag + (size_t)row*Kc + k0 + ldSeg*8;
            const __nv_bfloat16* bs = Bg + (size_t)row*Kc + k0 + ldSeg*8;
            cp16(asb + so, as);
            cp16(bsb + so, bs);
        }
    };

    load_tiles(0, 0);
    cp_commit();
    cp_wait0();
    __syncthreads();

    const int KT = Kc >> 5;
    for (int kt = 0; kt < KT; kt++) {
        int buf = kt & 1;
        if (kt + 1 < KT) { load_tiles(buf ^ 1, (kt + 1) << 5); cp_commit(); }
        uint32_t ab = asb + (uint32_t)(buf*BM*LDA*2);
        uint32_t bb = bsb + (uint32_t)(buf*BN*LDA*2);
        #pragma unroll
        for (int ks = 0; ks < 2; ks++) {
            uint32_t af[4][4], bf[2][4];
            #pragma unroll
            for (int mt = 0; mt < 4; mt++)
                ldsm_x4(af[mt][0], af[mt][1], af[mt][2], af[mt][3],
                        ab + (uint32_t)(((aRow + mt*16)*LDA + aColH + ks*16) * 2));
            #pragma unroll
            for (int p = 0; p < 2; p++)
                ldsm_x4(bf[p][0], bf[p][1], bf[p][2], bf[p][3],
                        bb + (uint32_t)(((bRow + p*16)*LDA + bColH + ks*16) * 2));
            #pragma unroll
            for (int mt = 0; mt < 4; mt++)
                #pragma unroll
                for (int nt = 0; nt < 4; nt++)
                    mma16816(acc[mt][nt], af[mt], &bf[nt >> 1][(nt & 1) * 2]);
        }
        if (kt + 1 < KT) cp_wait0();
        __syncthreads();
    }

    // ---------------- epilogue: registers -> global ----------------
    const int mbase = blockIdx.y*BM + warpM*64 + (lane >> 2);
    #pragma unroll
    for (int nt = 0; nt < 4; nt++) {
        int coll = warpN*32 + nt*8 + (lane & 3)*2;        // local col within 128
        if (NSTORE < BN && coll >= NSTORE) continue;
        int gcol = blockIdx.x*BN + coll;
        float bx = 0.f, by = 0.f;
        if (BIAS) { bx = __ldg(&bias[gcol]); by = __ldg(&bias[gcol + 1]); }
        #pragma unroll
        for (int mt = 0; mt < 4; mt++) {
            float2 v0 = make_float2(acc[mt][nt][0] + bx, acc[mt][nt][1] + by);
            float2 v1 = make_float2(acc[mt][nt][2] + bx, acc[mt][nt][3] + by);
            if (RELU) {
                v0.x = fmaxf(v0.x, 0.f); v0.y = fmaxf(v0.y, 0.f);
                v1.x = fmaxf(v1.x, 0.f); v1.y = fmaxf(v1.y, 0.f);
            }
            size_t r0 = (size_t)(mbase + mt*16);
            *(float2*)&C[r0*ldc + gcol]       = v0;
            *(float2*)&C[(r0 + 8)*ldc + gcol] = v1;
        }
    }
}

// ---------------- depthwise causal conv(4) + SiLU (+ hi/lo cat) -------------
__global__ void conv_silu_kernel(const float* __restrict__ cw, const float* __restrict__ cb,
                                 __nv_bfloat16* __restrict__ ucat) {
    int m = blockIdx.x;
    int d = threadIdx.x;
    int l = m & (SEQ - 1);
    float4 w4 = ((const float4*)cw)[d];
    const float* xc = g_XZ + (size_t)m * (2*DI) + d;
    float acc = cb[d] + w4.w * xc[0];
    if (l >= 1) acc += w4.z * xc[-(2*DI)];
    if (l >= 2) acc += w4.y * xc[-2*(2*DI)];
    if (l >= 3) acc += w4.x * xc[-3*(2*DI)];
    float u = acc * (1.0f / (1.0f + __expf(-acc)));
    g_U[(size_t)m*DI + d] = u;
    unsigned short h, lo;
    split_bf(u, h, lo);
    __nv_bfloat16* oc = ucat + (size_t)m*768 + d;
    oc[0]   = __ushort_as_bfloat16(h);
    oc[256] = __ushort_as_bfloat16(lo);
    oc[512] = __ushort_as_bfloat16(h);
}

// ---------------- dt = softplus(DBC[:, :8] @ Wdt[8,256] + b_dt) -------------
__global__ __launch_bounds__(256) void dt_kernel(const float* __restrict__ Wdt,
                                                 const float* __restrict__ bdt) {
    __shared__ float Ws[DR*DI];
    for (int i = threadIdx.x; i < DR*DI; i += 256) Ws[i] = Wdt[i];
    __syncthreads();
    int d  = threadIdx.x;
    float bv = bdt[d];
    int m0 = blockIdx.x * 16;
    for (int p = 0; p < 16; p++) {
        int m = m0 + p;
        const float* r = g_DBC + (size_t)m * DXPP;
        float acc = bv;
        #pragma unroll
        for (int j = 0; j < DR; j++) acc += r[j] * Ws[j*DI + d];
        g_DT[(size_t)m*DI + d] = (acc > 20.f) ? acc : log1pf(__expf(acc));
    }
}

// ---------------- selective scan (writes hi/lo cat Y directly) --------------
__global__ __launch_bounds__(256) void scan_kernel(const float* __restrict__ A_log,
                                                   const float* __restrict__ D_skip,
                                                   __nv_bfloat16* __restrict__ ycat) {
    int warp = threadIdx.x >> 5;
    int lane = threadIdx.x & 31;
    int half = lane >> 4;
    int s    = lane & 15;
    int ch   = blockIdx.x * 16 + warp * 2 + half;
    int b    = ch >> 8;
    int d    = ch & 255;
    float a   = -__expf(A_log[d*DS + s]);
    float dsk = D_skip[d];
    float h   = 0.f;
    size_t m  = (size_t)b * SEQ;
    #pragma unroll 2
    for (int l = 0; l < SEQ; l++, m++) {
        float dtv = g_DT[m*DI + d];
        float uv  = g_U [m*DI + d];
        float Bv  = g_DBC[m*DXPP + DR + s];
        float Cv  = g_DBC[m*DXPP + DR + DS + s];
        h = __expf(dtv * a) * h + dtv * uv * Bv;
        float y = h * Cv;
        y += __shfl_xor_sync(0xffffffffu, y, 8);
        y += __shfl_xor_sync(0xffffffffu, y, 4);
        y += __shfl_xor_sync(0xffffffffu, y, 2);
        y += __shfl_xor_sync(0xffffffffu, y, 1);
        if (s == 0) {
            float zv  = g_XZ[m*(2*DI) + DI + d];
            float val = (y + uv * dsk) * (zv / (1.0f + __expf(-zv)));
            unsigned short hh, ll;
            split_bf(val, hh, ll);
            __nv_bfloat16* oc = ycat + m*768 + d;
            oc[0]   = __ushort_as_bfloat16(hh);
            oc[256] = __ushort_as_bfloat16(ll);
            oc[512] = __ushort_as_bfloat16(hh);
        }
    }
}

// ---------------- host launch ----------------
extern "C" void kernel_launch(void* const* d_in, const int* in_sizes, int n_in,
                              void* d_out, int out_size) {
    const int*   tokens  = (const int*)  d_in[0];
    const float* emb     = (const float*)d_in[1];
    const float* ln_w    = (const float*)d_in[2];
    const float* ln_b    = (const float*)d_in[3];
    const float* W_in    = (const float*)d_in[4];
    const float* conv_w  = (const float*)d_in[5];
    const float* conv_b  = (const float*)d_in[6];
    const float* W_xproj = (const float*)d_in[7];
    const float* W_dt    = (const float*)d_in[8];
    const float* b_dt    = (const float*)d_in[9];
    const float* A_log   = (const float*)d_in[10];
    const float* D_skip  = (const float*)d_in[11];
    const float* W_out   = (const float*)d_in[12];
    const float* W1      = (const float*)d_in[13];
    const float* b1      = (const float*)d_in[14];
    const float* W2      = (const float*)d_in[15];
    const float* b2      = (const float*)d_in[16];
    float* out = (float*)d_out;

    float *X, *XZ, *DBC, *H;
    __nv_bfloat16 *Acat, *Bcat;
    cudaGetSymbolAddress((void**)&X,    g_X);
    cudaGetSymbolAddress((void**)&XZ,   g_XZ);
    cudaGetSymbolAddress((void**)&DBC,  g_DBC);
    cudaGetSymbolAddress((void**)&H,    g_H);
    cudaGetSymbolAddress((void**)&Acat, g_Acat);
    cudaGetSymbolAddress((void**)&Bcat, g_Bcat);

    embed_kernel<<<MTOT*32/256, 256>>>(tokens, emb);

    for (int layer = 0; layer < NL; layer++) {
        // LN + split-bf16 cat (Kc = 3*128 = 384)
        ln_cvt_kernel<<<MTOT/8, 256>>>(ln_w + layer*DM, ln_b + layer*DM, X, Acat);
        // xz = xn @ W_in : [32768,128]x[128,512]
        cvtB_kernel<<<512*128/256, 256>>>(W_in + (size_t)layer*DM*2*DI, Bcat, DM, 2*DI, 2*DI);
        mma_gemm_kernel<128,false,false><<<dim3(4, 256), 256>>>(
            384, Acat, Bcat, nullptr, XZ, 2*DI);
        // conv + silu (+ cat for xproj, Kc = 3*256 = 768)
        conv_silu_kernel<<<MTOT, DI>>>(conv_w + (size_t)layer*DI*4,
                                       conv_b + (size_t)layer*DI, Acat);
        // dbc = u @ W_xproj : [32768,256]x[256,40], B padded to 128 rows
        cvtB_kernel<<<128*256/256, 256>>>(W_xproj + (size_t)layer*DI*40, Bcat, DI, 40, 128);
        mma_gemm_kernel<64,false,false><<<dim3(1, 256), 256>>>(
            768, Acat, Bcat, nullptr, DBC, DXPP);
        // dt
        dt_kernel<<<MTOT/16, 256>>>(W_dt + (size_t)layer*DR*DI, b_dt + (size_t)layer*DI);
        // selective scan + gating (+ cat for W_out)
        scan_kernel<<<BATCH*DI/16, 256>>>(A_log  + (size_t)layer*DI*DS,
                                          D_skip + (size_t)layer*DI, Acat);
        // x = y @ W_out : [32768,256]x[256,128]
        cvtB_kernel<<<128*256/256, 256>>>(W_out + (size_t)layer*DI*DM, Bcat, DI, DM, DM);
        mma_gemm_kernel<128,false,false><<<dim3(1, 256), 256>>>(
            768, Acat, Bcat, nullptr, X, DM);
    }

    // h = relu(x @ W1 + b1) : [32768,128]x[128,512]
    cvtA_kernel<<<MTOT*DM/4/256, 256>>>(X, Acat, DM);
    cvtB_kernel<<<512*128/256, 256>>>(W1, Bcat, DM, DFF, DFF);
    mma_gemm_kernel<128,true,true><<<dim3(4, 256), 256>>>(
        384, Acat, Bcat, b1, H, DFF);
    // out = h @ W2 + b2 : [32768,512]x[512,4096]
    cvtA_kernel<<<MTOT*DFF/4/256, 256>>>(H, Acat, DFF);
    cvtB_kernel<<<(size_t)VOCABSZ*DFF/256, 256>>>(W2, Bcat, DFF, VOCABSZ, VOCABSZ);
    mma_gemm_kernel<128,true,false><<<dim3(VOCABSZ/128, 256), 256>>>(
        1536, Acat, Bcat, b2, out, VOCABSZ);
}

// round 8
// speedup vs baseline: 3.6830x; 3.5135x over previous
#include <cuda_runtime.h>
#include <cuda_bf16.h>
#include <stdint.h>
#include <math.h>

// ---------------- problem constants ----------------
#define BATCH   8
#define SEQ     4096
#define MTOT    (BATCH*SEQ)      // 32768
#define DM      128              // d_model
#define DI      256              // d_inner
#define DS      16               // d_state
#define DR      8                // dt_rank
#define DXPP    64               // padded xproj out (real 40)
#define DFF     512
#define VOCABSZ 4096
#define NL      4
#define TSS     64               // scan tile steps

// ---------------- device scratch (no allocations allowed) ----------------
__device__ __align__(16) float g_X  [MTOT*DM];        // 16 MB
__device__ __align__(16) float g_XZ [MTOT*2*DI];      // 64 MB
__device__ __align__(16) float g_U  [MTOT*DI];        // 32 MB
__device__ __align__(16) float g_DBC[MTOT*DXPP];      //  8 MB
__device__ __align__(16) float g_DT [MTOT*DI];        // 32 MB
__device__ __align__(16) float g_H  [MTOT*DFF];       // 64 MB
__device__ __align__(16) float g_DTt[(size_t)BATCH*DI*SEQ];  // 32 MB channel-major
__device__ __align__(16) float g_Ut [(size_t)BATCH*DI*SEQ];  // 32 MB
__device__ __align__(16) float g_Zt [(size_t)BATCH*DI*SEQ];  // 32 MB
__device__ __align__(16) __nv_bfloat16 g_Acat[(size_t)MTOT*1536];   // 96 MB
__device__ __align__(16) __nv_bfloat16 g_Bcat[(size_t)VOCABSZ*1536];// 12 MB

// ---------------- helpers ----------------
__device__ __forceinline__ uint32_t smem_u32(const void* p) {
    uint32_t a;
    asm("{ .reg .u64 t; cvta.to.shared.u64 t, %1; cvt.u32.u64 %0, t; }" : "=r"(a) : "l"(p));
    return a;
}
__device__ __forceinline__ void cp16(uint32_t dst, const void* src) {
    asm volatile("cp.async.cg.shared.global [%0], [%1], 16;" :: "r"(dst), "l"(src));
}
__device__ __forceinline__ void cp_commit() {
    asm volatile("cp.async.commit_group;" ::: "memory");
}
__device__ __forceinline__ void cp_wait0() {
    asm volatile("cp.async.wait_group 0;" ::: "memory");
}
__device__ __forceinline__ void ldsm_x4(uint32_t& r0, uint32_t& r1, uint32_t& r2,
                                        uint32_t& r3, uint32_t addr) {
    asm volatile("ldmatrix.sync.aligned.m8n8.x4.shared.b16 {%0,%1,%2,%3}, [%4];"
                 : "=r"(r0), "=r"(r1), "=r"(r2), "=r"(r3) : "r"(addr));
}
__device__ __forceinline__ void mma16816(float* c, const uint32_t* a, const uint32_t* b) {
    asm volatile("mma.sync.aligned.m16n8k16.row.col.f32.bf16.bf16.f32 "
                 "{%0,%1,%2,%3},{%4,%5,%6,%7},{%8,%9},{%0,%1,%2,%3};"
                 : "+f"(c[0]), "+f"(c[1]), "+f"(c[2]), "+f"(c[3])
                 : "r"(a[0]), "r"(a[1]), "r"(a[2]), "r"(a[3]), "r"(b[0]), "r"(b[1]));
}
__device__ __forceinline__ void split_bf(float x, unsigned short& h, unsigned short& l) {
    __nv_bfloat16 hb = __float2bfloat16(x);
    __nv_bfloat16 lb = __float2bfloat16(x - __bfloat162float(hb));
    h = __bfloat16_as_ushort(hb);
    l = __bfloat16_as_ushort(lb);
}

// ---------------- embedding gather ----------------
__global__ void embed_kernel(const int* __restrict__ tokens,
                             const float* __restrict__ emb) {
    int idx = blockIdx.x * blockDim.x + threadIdx.x;
    int m = idx >> 5, c4 = idx & 31;
    int t = tokens[m];
    ((float4*)g_X)[(size_t)m*32 + c4] = ((const float4*)emb)[(size_t)t*32 + c4];
}

// ---------------- layernorm fused with hi/lo bf16 cat: out [M, 384] ----------
__global__ void ln_cvt_kernel(const float* __restrict__ w, const float* __restrict__ b,
                              const float* __restrict__ X, __nv_bfloat16* __restrict__ out) {
    int gw   = (blockIdx.x * blockDim.x + threadIdx.x) >> 5;
    int lane = threadIdx.x & 31;
    float4 v = ((const float4*)X)[(size_t)gw*32 + lane];
    float s = v.x + v.y + v.z + v.w;
    #pragma unroll
    for (int o = 16; o; o >>= 1) s += __shfl_xor_sync(0xffffffffu, s, o);
    float mu = s * (1.0f/DM);
    float dx = v.x-mu, dy = v.y-mu, dz = v.z-mu, dw = v.w-mu;
    float q = dx*dx + dy*dy + dz*dz + dw*dw;
    #pragma unroll
    for (int o = 16; o; o >>= 1) q += __shfl_xor_sync(0xffffffffu, q, o);
    float rstd = rsqrtf(q * (1.0f/DM) + 1e-5f);
    float4 w4 = ((const float4*)w)[lane];
    float4 b4 = ((const float4*)b)[lane];
    float o0 = dx*rstd*w4.x + b4.x;
    float o1 = dy*rstd*w4.y + b4.y;
    float o2 = dz*rstd*w4.z + b4.z;
    float o3 = dw*rstd*w4.w + b4.w;
    unsigned short h0,h1,h2,h3,l0,l1,l2,l3;
    split_bf(o0,h0,l0); split_bf(o1,h1,l1); split_bf(o2,h2,l2); split_bf(o3,h3,l3);
    uint32_t ph0 = h0 | ((uint32_t)h1<<16), ph1 = h2 | ((uint32_t)h3<<16);
    uint32_t pl0 = l0 | ((uint32_t)l1<<16), pl1 = l2 | ((uint32_t)l3<<16);
    uint32_t* ob = (uint32_t*)(out + (size_t)gw*384);
    ob[lane*2]       = ph0; ob[lane*2+1]       = ph1;   // hi  [0,128)
    ob[64 + lane*2]  = pl0; ob[64 + lane*2+1]  = pl1;   // lo  [128,256)
    ob[128 + lane*2] = ph0; ob[128 + lane*2+1] = ph1;   // hi  [256,384)
}

// ---------------- generic activation hi/lo cat: in [M,K] fp32 -> out [M,3K] --
__global__ void cvtA_kernel(const float* __restrict__ in, __nv_bfloat16* __restrict__ out,
                            int K) {
    int i4 = blockIdx.x * blockDim.x + threadIdx.x;
    int kq = K >> 2;
    int m  = i4 / kq;
    int k  = (i4 - m*kq) << 2;
    float4 v = ((const float4*)in)[i4];
    unsigned short h0,h1,h2,h3,l0,l1,l2,l3;
    split_bf(v.x,h0,l0); split_bf(v.y,h1,l1); split_bf(v.z,h2,l2); split_bf(v.w,h3,l3);
    uint32_t ph0 = h0 | ((uint32_t)h1<<16), ph1 = h2 | ((uint32_t)h3<<16);
    uint32_t pl0 = l0 | ((uint32_t)l1<<16), pl1 = l2 | ((uint32_t)l3<<16);
    uint32_t* o = (uint32_t*)(out + (size_t)m*3*K);
    int ki = k >> 1;
    o[ki] = ph0;              o[ki+1] = ph1;
    o[(K>>1)+ki] = pl0;       o[(K>>1)+ki+1] = pl1;
    o[K+ki] = ph0;            o[K+ki+1] = ph1;
}

// ------------- weight transpose + hi/lo cat: W [K,N] fp32 -> out [Npad,3K] ---
// pairing: B = [hi | hi | lo]  (A = [hi | lo | hi])
__global__ void cvtB_kernel(const float* __restrict__ W, __nv_bfloat16* __restrict__ out,
                            int K, int N, int Npad) {
    int idx = blockIdx.x * blockDim.x + threadIdx.x;   // over Npad*K
    int n = idx / K, k = idx - n*K;
    float v = (n < N) ? W[(size_t)k*N + n] : 0.f;
    unsigned short h, l;
    split_bf(v, h, l);
    __nv_bfloat16* o = out + (size_t)n*3*K;
    o[k]       = __ushort_as_bfloat16(h);
    o[K + k]   = __ushort_as_bfloat16(h);
    o[2*K + k] = __ushort_as_bfloat16(l);
}

// ---------------- HMMA bf16 GEMM: D[m,n] = sum_k A[m,k]*B[n,k] ---------------
template<int NSTORE, bool BIAS, bool RELU>
__global__ __launch_bounds__(256, 2) void mma_gemm_kernel(
    int Kc, const __nv_bfloat16* __restrict__ A, const __nv_bfloat16* __restrict__ B,
    const float* __restrict__ bias, float* __restrict__ C, int ldc)
{
    constexpr int BM = 128, BN = 128, LDA = 40;   // 32 + 8 pad halves (80B row)
    __shared__ __align__(16) __nv_bfloat16 As[2][BM*LDA];
    __shared__ __align__(16) __nv_bfloat16 Bs[2][BN*LDA];
    const int tid = threadIdx.x, wid = tid >> 5, lane = tid & 31;
    const int warpM = wid >> 2, warpN = wid & 3;

    const __nv_bfloat16* Ag = A + (size_t)blockIdx.y * BM * Kc;
    const __nv_bfloat16* Bg = B + (size_t)blockIdx.x * BN * Kc;
    const uint32_t asb = smem_u32(As);
    const uint32_t bsb = smem_u32(Bs);

    const int ldRow = tid >> 2, ldSeg = tid & 3;

    float acc[4][4][4];
    #pragma unroll
    for (int i = 0; i < 4; i++)
        #pragma unroll
        for (int j = 0; j < 4; j++)
            #pragma unroll
            for (int q = 0; q < 4; q++) acc[i][j][q] = 0.f;

    const int aRow  = warpM*64 + (lane & 15);
    const int aColH = (lane >> 4) * 8;
    const int bRow  = warpN*32 + (lane & 7) + ((lane >> 4) & 1) * 8;
    const int bColH = ((lane >> 3) & 1) * 8;

    auto load_tiles = [&](int buf, int k0) {
        #pragma unroll
        for (int i = 0; i < 2; i++) {
            int row = ldRow + i*64;
            uint32_t so = (uint32_t)((buf*BM*LDA + row*LDA + ldSeg*8) * 2);
            const __nv_bfloat16* as = Ag + (size_t)row*Kc + k0 + ldSeg*8;
            const __nv_bfloat16* bs = Bg + (size_t)row*Kc + k0 + ldSeg*8;
            cp16(asb + so, as);
            cp16(bsb + so, bs);
        }
    };

    load_tiles(0, 0);
    cp_commit();
    cp_wait0();
    __syncthreads();

    const int KT = Kc >> 5;
    for (int kt = 0; kt < KT; kt++) {
        int buf = kt & 1;
        if (kt + 1 < KT) { load_tiles(buf ^ 1, (kt + 1) << 5); cp_commit(); }
        uint32_t ab = asb + (uint32_t)(buf*BM*LDA*2);
        uint32_t bb = bsb + (uint32_t)(buf*BN*LDA*2);
        #pragma unroll
        for (int ks = 0; ks < 2; ks++) {
            uint32_t af[4][4], bf[2][4];
            #pragma unroll
            for (int mt = 0; mt < 4; mt++)
                ldsm_x4(af[mt][0], af[mt][1], af[mt][2], af[mt][3],
                        ab + (uint32_t)(((aRow + mt*16)*LDA + aColH + ks*16) * 2));
            #pragma unroll
            for (int p = 0; p < 2; p++)
                ldsm_x4(bf[p][0], bf[p][1], bf[p][2], bf[p][3],
                        bb + (uint32_t)(((bRow + p*16)*LDA + bColH + ks*16) * 2));
            #pragma unroll
            for (int mt = 0; mt < 4; mt++)
                #pragma unroll
                for (int nt = 0; nt < 4; nt++)
                    mma16816(acc[mt][nt], af[mt], &bf[nt >> 1][(nt & 1) * 2]);
        }
        if (kt + 1 < KT) cp_wait0();
        __syncthreads();
    }

    const int mbase = blockIdx.y*BM + warpM*64 + (lane >> 2);
    #pragma unroll
    for (int nt = 0; nt < 4; nt++) {
        int coll = warpN*32 + nt*8 + (lane & 3)*2;
        if (NSTORE < BN && coll >= NSTORE) continue;
        int gcol = blockIdx.x*BN + coll;
        float bx = 0.f, by = 0.f;
        if (BIAS) { bx = __ldg(&bias[gcol]); by = __ldg(&bias[gcol + 1]); }
        #pragma unroll
        for (int mt = 0; mt < 4; mt++) {
            float2 v0 = make_float2(acc[mt][nt][0] + bx, acc[mt][nt][1] + by);
            float2 v1 = make_float2(acc[mt][nt][2] + bx, acc[mt][nt][3] + by);
            if (RELU) {
                v0.x = fmaxf(v0.x, 0.f); v0.y = fmaxf(v0.y, 0.f);
                v1.x = fmaxf(v1.x, 0.f); v1.y = fmaxf(v1.y, 0.f);
            }
            size_t r0 = (size_t)(mbase + mt*16);
            *(float2*)&C[r0*ldc + gcol]       = v0;
            *(float2*)&C[(r0 + 8)*ldc + gcol] = v1;
        }
    }
}

// ---------------- depthwise causal conv(4) + SiLU (+ hi/lo cat) -------------
__global__ void conv_silu_kernel(const float* __restrict__ cw, const float* __restrict__ cb,
                                 __nv_bfloat16* __restrict__ ucat) {
    int m = blockIdx.x;
    int d = threadIdx.x;
    int l = m & (SEQ - 1);
    float4 w4 = ((const float4*)cw)[d];
    const float* xc = g_XZ + (size_t)m * (2*DI) + d;
    float acc = cb[d] + w4.w * xc[0];
    if (l >= 1) acc += w4.z * xc[-(2*DI)];
    if (l >= 2) acc += w4.y * xc[-2*(2*DI)];
    if (l >= 3) acc += w4.x * xc[-3*(2*DI)];
    float u = acc * (1.0f / (1.0f + __expf(-acc)));
    g_U[(size_t)m*DI + d] = u;
    unsigned short h, lo;
    split_bf(u, h, lo);
    __nv_bfloat16* oc = ucat + (size_t)m*768 + d;
    oc[0]   = __ushort_as_bfloat16(h);
    oc[256] = __ushort_as_bfloat16(lo);
    oc[512] = __ushort_as_bfloat16(h);
}

// ---------------- dt = softplus(DBC[:, :8] @ Wdt[8,256] + b_dt) -------------
__global__ __launch_bounds__(256) void dt_kernel(const float* __restrict__ Wdt,
                                                 const float* __restrict__ bdt) {
    __shared__ float Ws[DR*DI];
    for (int i = threadIdx.x; i < DR*DI; i += 256) Ws[i] = Wdt[i];
    __syncthreads();
    int d  = threadIdx.x;
    float bv = bdt[d];
    int m0 = blockIdx.x * 16;
    for (int p = 0; p < 16; p++) {
        int m = m0 + p;
        const float* r = g_DBC + (size_t)m * DXPP;
        float acc = bv;
        #pragma unroll
        for (int j = 0; j < DR; j++) acc += r[j] * Ws[j*DI + d];
        g_DT[(size_t)m*DI + d] = (acc > 20.f) ? acc : log1pf(__expf(acc));
    }
}

// -------- tiled transpose: dt/u/z token-major -> channel-major [b*DI+d][L] --
__global__ void trans_kernel() {
    __shared__ float t0[32][33];
    __shared__ float t1[32][33];
    __shared__ float t2[32][33];
    int l0 = blockIdx.x * 32, d0 = blockIdx.y * 32, b = blockIdx.z;
    int tx = threadIdx.x, ty = threadIdx.y;
    #pragma unroll
    for (int i = ty; i < 32; i += 8) {
        size_t m = (size_t)b*SEQ + l0 + i;
        t0[i][tx] = g_DT[m*DI + d0 + tx];
        t1[i][tx] = g_U [m*DI + d0 + tx];
        t2[i][tx] = g_XZ[m*2*DI + DI + d0 + tx];
    }
    __syncthreads();
    #pragma unroll
    for (int i = ty; i < 32; i += 8) {
        size_t ch = (size_t)b*DI + d0 + i;
        g_DTt[ch*SEQ + l0 + tx] = t0[tx][i];
        g_Ut [ch*SEQ + l0 + tx] = t1[tx][i];
        g_Zt [ch*SEQ + l0 + tx] = t2[tx][i];
    }
}

// ---------------- selective scan v2: smem-staged, cp.async double-buffered --
// block = 16 channels of one batch x 16 states; warp = 2 channels.
__global__ __launch_bounds__(256) void scan_kernel(const float* __restrict__ A_log,
                                                   const float* __restrict__ D_skip,
                                                   __nv_bfloat16* __restrict__ ycat) {
    __shared__ __align__(16) float dts[2][16][TSS];
    __shared__ __align__(16) float us [2][16][TSS];
    __shared__ __align__(16) float zs [2][16][TSS];
    __shared__ __align__(16) float bcs[2][TSS][32];
    const int tid = threadIdx.x, warp = tid >> 5, lane = tid & 31;
    const int half = lane >> 4, s = lane & 15;
    const int b  = blockIdx.x >> 4;            // 16 blocks per batch
    const int dg = (blockIdx.x & 15) << 4;     // channel group base
    const int chl = warp*2 + half;             // local channel 0..15
    const int d = dg + chl;
    const float a   = -__expf(A_log[d*DS + s]);
    const float dsk = D_skip[d];
    const float* dtp = g_DTt + ((size_t)b*DI + dg)*SEQ;
    const float* up  = g_Ut  + ((size_t)b*DI + dg)*SEQ;
    const float* zp  = g_Zt  + ((size_t)b*DI + dg)*SEQ;
    const float* bcp = g_DBC + (size_t)b*SEQ*DXPP;

    const int lrow = tid >> 4, lseg = tid & 15;   // dt/u/z tile: 16 rows x 16 segs

    auto load_tile = [&](int buf, int l0) {
        size_t goff = (size_t)lrow*SEQ + l0 + lseg*4;
        cp16(smem_u32(&dts[buf][lrow][lseg*4]), dtp + goff);
        cp16(smem_u32(&us [buf][lrow][lseg*4]), up  + goff);
        cp16(smem_u32(&zs [buf][lrow][lseg*4]), zp  + goff);
        #pragma unroll
        for (int r = 0; r < 2; r++) {
            int idx = tid + r*256;
            int j = idx >> 3, seg = idx & 7;
            cp16(smem_u32(&bcs[buf][j][seg*4]),
                 bcp + (size_t)(l0 + j)*DXPP + DR + seg*4);
        }
        cp_commit();
    };

    load_tile(0, 0);
    float h = 0.f;
    const int NT = SEQ / TSS;
    for (int t = 0; t < NT; t++) {
        int buf = t & 1;
        cp_wait0();          // tile t resident
        __syncthreads();     // all threads done with buf^1 compute, see smem
        if (t + 1 < NT) load_tile(buf ^ 1, (t + 1) * TSS);
        #pragma unroll 4
        for (int j = 0; j < TSS; j++) {
            float dtv = dts[buf][chl][j];
            float uv  = us [buf][chl][j];
            float Bv  = bcs[buf][j][s];
            float Cv  = bcs[buf][j][16 + s];
            h = __expf(dtv * a) * h + dtv * uv * Bv;
            float y = h * Cv;
            y += __shfl_xor_sync(0xffffffffu, y, 8);
            y += __shfl_xor_sync(0xffffffffu, y, 4);
            y += __shfl_xor_sync(0xffffffffu, y, 2);
            y += __shfl_xor_sync(0xffffffffu, y, 1);
            if (s == 0) {
                float zv  = zs[buf][chl][j];
                float val = (y + uv * dsk) * (zv / (1.0f + __expf(-zv)));
                unsigned short hh, ll;
                split_bf(val, hh, ll);
                size_t m = (size_t)b*SEQ + t*TSS + j;
                __nv_bfloat16* oc = ycat + m*768 + d;
                oc[0]   = __ushort_as_bfloat16(hh);
                oc[256] = __ushort_as_bfloat16(ll);
                oc[512] = __ushort_as_bfloat16(hh);
            }
        }
    }
}

// ---------------- host launch ----------------
extern "C" void kernel_launch(void* const* d_in, const int* in_sizes, int n_in,
                              void* d_out, int out_size) {
    const int*   tokens  = (const int*)  d_in[0];
    const float* emb     = (const float*)d_in[1];
    const float* ln_w    = (const float*)d_in[2];
    const float* ln_b    = (const float*)d_in[3];
    const float* W_in    = (const float*)d_in[4];
    const float* conv_w  = (const float*)d_in[5];
    const float* conv_b  = (const float*)d_in[6];
    const float* W_xproj = (const float*)d_in[7];
    const float* W_dt    = (const float*)d_in[8];
    const float* b_dt    = (const float*)d_in[9];
    const float* A_log   = (const float*)d_in[10];
    const float* D_skip  = (const float*)d_in[11];
    const float* W_out   = (const float*)d_in[12];
    const float* W1      = (const float*)d_in[13];
    const float* b1      = (const float*)d_in[14];
    const float* W2      = (const float*)d_in[15];
    const float* b2      = (const float*)d_in[16];
    float* out = (float*)d_out;

    float *X, *XZ, *DBC, *H;
    __nv_bfloat16 *Acat, *Bcat;
    cudaGetSymbolAddress((void**)&X,    g_X);
    cudaGetSymbolAddress((void**)&XZ,   g_XZ);
    cudaGetSymbolAddress((void**)&DBC,  g_DBC);
    cudaGetSymbolAddress((void**)&H,    g_H);
    cudaGetSymbolAddress((void**)&Acat, g_Acat);
    cudaGetSymbolAddress((void**)&Bcat, g_Bcat);

    embed_kernel<<<MTOT*32/256, 256>>>(tokens, emb);

    for (int layer = 0; layer < NL; layer++) {
        // LN + split-bf16 cat (Kc = 3*128 = 384)
        ln_cvt_kernel<<<MTOT/8, 256>>>(ln_w + layer*DM, ln_b + layer*DM, X, Acat);
        // xz = xn @ W_in : [32768,128]x[128,512]
        cvtB_kernel<<<512*128/256, 256>>>(W_in + (size_t)layer*DM*2*DI, Bcat, DM, 2*DI, 2*DI);
        mma_gemm_kernel<128,false,false><<<dim3(4, 256), 256>>>(
            384, Acat, Bcat, nullptr, XZ, 2*DI);
        // conv + silu (+ cat for xproj, Kc = 3*256 = 768)
        conv_silu_kernel<<<MTOT, DI>>>(conv_w + (size_t)layer*DI*4,
                                       conv_b + (size_t)layer*DI, Acat);
        // dbc = u @ W_xproj : [32768,256]x[256,40], B padded to 128 rows
        cvtB_kernel<<<128*256/256, 256>>>(W_xproj + (size_t)layer*DI*40, Bcat, DI, 40, 128);
        mma_gemm_kernel<64,false,false><<<dim3(1, 256), 256>>>(
            768, Acat, Bcat, nullptr, DBC, DXPP);
        // dt
        dt_kernel<<<MTOT/16, 256>>>(W_dt + (size_t)layer*DR*DI, b_dt + (size_t)layer*DI);
        // transpose dt/u/z to channel-major for the scan
        trans_kernel<<<dim3(SEQ/32, DI/32, BATCH), dim3(32, 8)>>>();
        // selective scan + gating (+ cat for W_out)
        scan_kernel<<<BATCH*DI/16, 256>>>(A_log  + (size_t)layer*DI*DS,
                                          D_skip + (size_t)layer*DI, Acat);
        // x = y @ W_out : [32768,256]x[256,128]
        cvtB_kernel<<<128*256/256, 256>>>(W_out + (size_t)layer*DI*DM, Bcat, DI, DM, DM);
        mma_gemm_kernel<128,false,false><<<dim3(1, 256), 256>>>(
            768, Acat, Bcat, nullptr, X, DM);
    }

    // h = relu(x @ W1 + b1) : [32768,128]x[128,512]
    cvtA_kernel<<<MTOT*DM/4/256, 256>>>(X, Acat, DM);
    cvtB_kernel<<<512*128/256, 256>>>(W1, Bcat, DM, DFF, DFF);
    mma_gemm_kernel<128,true,true><<<dim3(4, 256), 256>>>(
        384, Acat, Bcat, b1, H, DFF);
    // out = h @ W2 + b2 : [32768,512]x[512,4096]
    cvtA_kernel<<<MTOT*DFF/4/256, 256>>>(H, Acat, DFF);
    cvtB_kernel<<<(size_t)VOCABSZ*DFF/256, 256>>>(W2, Bcat, DFF, VOCABSZ, VOCABSZ);
    mma_gemm_kernel<128,true,false><<<dim3(VOCABSZ/128, 256), 256>>>(
        1536, Acat, Bcat, b2, out, VOCABSZ);
}

// round 11
// speedup vs baseline: 3.7182x; 1.0096x over previous
#include <cuda_runtime.h>
#include <cuda_bf16.h>
#include <stdint.h>
#include <math.h>

// ---------------- problem constants ----------------
#define BATCH   8
#define SEQ     4096
#define MTOT    (BATCH*SEQ)      // 32768
#define DM      128              // d_model
#define DI      256              // d_inner
#define DS      16               // d_state
#define DR      8                // dt_rank
#define DXPP    64               // padded xproj out (real 40)
#define DFF     512
#define VOCABSZ 4096
#define NL      4
#define TSS     64               // scan tile steps

// ---------------- device scratch (no allocations allowed) ----------------
__device__ __align__(16) float g_X  [MTOT*DM];        // 16 MB
__device__ __align__(16) float g_XZ [MTOT*2*DI];      // 64 MB
__device__ __align__(16) float g_U  [MTOT*DI];        // 32 MB
__device__ __align__(16) float g_DBC[MTOT*DXPP];      //  8 MB
__device__ __align__(16) float g_DT [MTOT*DI];        // 32 MB
__device__ __align__(16) float g_H  [MTOT*DFF];       // 64 MB
__device__ __align__(16) float g_DTt[(size_t)BATCH*DI*SEQ];  // 32 MB channel-major
__device__ __align__(16) float g_Ut [(size_t)BATCH*DI*SEQ];  // 32 MB
__device__ __align__(16) float g_Zt [(size_t)BATCH*DI*SEQ];  // 32 MB
__device__ __align__(16) __nv_bfloat16 g_Acat[(size_t)MTOT*1536];   // 96 MB
__device__ __align__(16) __nv_bfloat16 g_Bcat[(size_t)VOCABSZ*1536];// 12 MB

// ---------------- helpers ----------------
__device__ __forceinline__ uint32_t smem_u32(const void* p) {
    uint32_t a;
    asm("{ .reg .u64 t; cvta.to.shared.u64 t, %1; cvt.u32.u64 %0, t; }" : "=r"(a) : "l"(p));
    return a;
}
__device__ __forceinline__ void cp16(uint32_t dst, const void* src) {
    asm volatile("cp.async.cg.shared.global [%0], [%1], 16;" :: "r"(dst), "l"(src));
}
__device__ __forceinline__ void cp_commit() {
    asm volatile("cp.async.commit_group;" ::: "memory");
}
__device__ __forceinline__ void cp_wait0() {
    asm volatile("cp.async.wait_group 0;" ::: "memory");
}
__device__ __forceinline__ void cp_wait1() {
    asm volatile("cp.async.wait_group 1;" ::: "memory");
}
__device__ __forceinline__ void ldsm_x4(uint32_t& r0, uint32_t& r1, uint32_t& r2,
                                        uint32_t& r3, uint32_t addr) {
    asm volatile("ldmatrix.sync.aligned.m8n8.x4.shared.b16 {%0,%1,%2,%3}, [%4];"
                 : "=r"(r0), "=r"(r1), "=r"(r2), "=r"(r3) : "r"(addr));
}
__device__ __forceinline__ void mma16816(float* c, const uint32_t* a, const uint32_t* b) {
    asm volatile("mma.sync.aligned.m16n8k16.row.col.f32.bf16.bf16.f32 "
                 "{%0,%1,%2,%3},{%4,%5,%6,%7},{%8,%9},{%0,%1,%2,%3};"
                 : "+f"(c[0]), "+f"(c[1]), "+f"(c[2]), "+f"(c[3])
                 : "r"(a[0]), "r"(a[1]), "r"(a[2]), "r"(a[3]), "r"(b[0]), "r"(b[1]));
}
__device__ __forceinline__ void split_bf(float x, unsigned short& h, unsigned short& l) {
    __nv_bfloat16 hb = __float2bfloat16(x);
    __nv_bfloat16 lb = __float2bfloat16(x - __bfloat162float(hb));
    h = __bfloat16_as_ushort(hb);
    l = __bfloat16_as_ushort(lb);
}

// ---------------- embedding gather ----------------
__global__ void embed_kernel(const int* __restrict__ tokens,
                             const float* __restrict__ emb) {
    int idx = blockIdx.x * blockDim.x + threadIdx.x;
    int m = idx >> 5, c4 = idx & 31;
    int t = tokens[m];
    ((float4*)g_X)[(size_t)m*32 + c4] = ((const float4*)emb)[(size_t)t*32 + c4];
}

// ---------------- layernorm fused with hi/lo bf16 cat: out [M, 384] ----------
__global__ void ln_cvt_kernel(const float* __restrict__ w, const float* __restrict__ b,
                              const float* __restrict__ X, __nv_bfloat16* __restrict__ out) {
    int gw   = (blockIdx.x * blockDim.x + threadIdx.x) >> 5;
    int lane = threadIdx.x & 31;
    float4 v = ((const float4*)X)[(size_t)gw*32 + lane];
    float s = v.x + v.y + v.z + v.w;
    #pragma unroll
    for (int o = 16; o; o >>= 1) s += __shfl_xor_sync(0xffffffffu, s, o);
    float mu = s * (1.0f/DM);
    float dx = v.x-mu, dy = v.y-mu, dz = v.z-mu, dw = v.w-mu;
    float q = dx*dx + dy*dy + dz*dz + dw*dw;
    #pragma unroll
    for (int o = 16; o; o >>= 1) q += __shfl_xor_sync(0xffffffffu, q, o);
    float rstd = rsqrtf(q * (1.0f/DM) + 1e-5f);
    float4 w4 = ((const float4*)w)[lane];
    float4 b4 = ((const float4*)b)[lane];
    float o0 = dx*rstd*w4.x + b4.x;
    float o1 = dy*rstd*w4.y + b4.y;
    float o2 = dz*rstd*w4.z + b4.z;
    float o3 = dw*rstd*w4.w + b4.w;
    unsigned short h0,h1,h2,h3,l0,l1,l2,l3;
    split_bf(o0,h0,l0); split_bf(o1,h1,l1); split_bf(o2,h2,l2); split_bf(o3,h3,l3);
    uint32_t ph0 = h0 | ((uint32_t)h1<<16), ph1 = h2 | ((uint32_t)h3<<16);
    uint32_t pl0 = l0 | ((uint32_t)l1<<16), pl1 = l2 | ((uint32_t)l3<<16);
    uint32_t* ob = (uint32_t*)(out + (size_t)gw*384);
    ob[lane*2]       = ph0; ob[lane*2+1]       = ph1;   // hi  [0,128)
    ob[64 + lane*2]  = pl0; ob[64 + lane*2+1]  = pl1;   // lo  [128,256)
    ob[128 + lane*2] = ph0; ob[128 + lane*2+1] = ph1;   // hi  [256,384)
}

// ---------------- generic activation hi/lo cat: in [M,K] fp32 -> out [M,3K] --
__global__ void cvtA_kernel(const float* __restrict__ in, __nv_bfloat16* __restrict__ out,
                            int K) {
    int i4 = blockIdx.x * blockDim.x + threadIdx.x;
    int kq = K >> 2;
    int m  = i4 / kq;
    int k  = (i4 - m*kq) << 2;
    float4 v = ((const float4*)in)[i4];
    unsigned short h0,h1,h2,h3,l0,l1,l2,l3;
    split_bf(v.x,h0,l0); split_bf(v.y,h1,l1); split_bf(v.z,h2,l2); split_bf(v.w,h3,l3);
    uint32_t ph0 = h0 | ((uint32_t)h1<<16), ph1 = h2 | ((uint32_t)h3<<16);
    uint32_t pl0 = l0 | ((uint32_t)l1<<16), pl1 = l2 | ((uint32_t)l3<<16);
    uint32_t* o = (uint32_t*)(out + (size_t)m*3*K);
    int ki = k >> 1;
    o[ki] = ph0;              o[ki+1] = ph1;
    o[(K>>1)+ki] = pl0;       o[(K>>1)+ki+1] = pl1;
    o[K+ki] = ph0;            o[K+ki+1] = ph1;
}

// ------------- weight transpose + hi/lo cat (smem-tiled, coalesced) ---------
// W [K,N] fp32 -> out [Npad,3K] bf16, pairing B = [hi | hi | lo]
__global__ void cvtB_kernel(const float* __restrict__ W, __nv_bfloat16* __restrict__ out,
                            int K, int N, int Npad) {
    __shared__ float t[32][33];
    int k0 = blockIdx.x * 32, n0 = blockIdx.y * 32;
    int tx = threadIdx.x, ty = threadIdx.y;
    #pragma unroll
    for (int i = ty; i < 32; i += 8)
        t[i][tx] = (n0 + tx < N) ? W[(size_t)(k0 + i)*N + n0 + tx] : 0.f;
    __syncthreads();
    #pragma unroll
    for (int i = ty; i < 32; i += 8) {
        int n = n0 + i;
        float v = t[tx][i];
        unsigned short h, l;
        split_bf(v, h, l);
        __nv_bfloat16* o = out + (size_t)n*3*K;
        o[k0 + tx]       = __ushort_as_bfloat16(h);
        o[K + k0 + tx]   = __ushort_as_bfloat16(h);
        o[2*K + k0 + tx] = __ushort_as_bfloat16(l);
    }
}

// ---------------- HMMA bf16 GEMM v2: D[m,n] = sum_k A[m,k]*B[n,k] ------------
// BM=256, BN=128, BK=32, 8 warps (4x2), warp tile 64x64, 3-stage cp.async.
template<int NSTORE, bool BIAS, bool RELU>
__global__ __launch_bounds__(256, 1) void mma_gemm_kernel(
    int Kc, const __nv_bfloat16* __restrict__ A, const __nv_bfloat16* __restrict__ B,
    const float* __restrict__ bias, float* __restrict__ C, int ldc)
{
    constexpr int BM = 256, BN = 128, LDA = 40;    // 32 + 8 pad halves (80B row)
    constexpr int ASZ = BM*LDA, BSZ = BN*LDA;      // halves per stage
    constexpr int STG = ASZ + BSZ;
    extern __shared__ __align__(16) __nv_bfloat16 sm[];
    const int tid = threadIdx.x, wid = tid >> 5, lane = tid & 31;
    const int warpM = wid >> 1, warpN = wid & 1;

    const __nv_bfloat16* Ag = A + (size_t)blockIdx.y * BM * Kc;
    const __nv_bfloat16* Bg = B + (size_t)blockIdx.x * BN * Kc;
    const uint32_t sb = smem_u32(sm);

    const int ldRow = tid >> 2, ldSeg = tid & 3;

    float acc[4][8][4];
    #pragma unroll
    for (int i = 0; i < 4; i++)
        #pragma unroll
        for (int j = 0; j < 8; j++)
            #pragma unroll
            for (int q = 0; q < 4; q++) acc[i][j][q] = 0.f;

    const int aRow  = warpM*64 + (lane & 15);
    const int aColH = (lane >> 4) * 8;
    const int bRow  = warpN*64 + (lane & 7) + ((lane >> 4) & 1) * 8;
    const int bColH = ((lane >> 3) & 1) * 8;

    auto load_tiles = [&](int st, int k0) {
        uint32_t ab = sb + (uint32_t)(st*STG*2);
        uint32_t bb = ab + (uint32_t)(ASZ*2);
        #pragma unroll
        for (int i = 0; i < 4; i++) {
            int row = ldRow + i*64;
            cp16(ab + (uint32_t)((row*LDA + ldSeg*8)*2),
                 Ag + (size_t)row*Kc + k0 + ldSeg*8);
        }
        #pragma unroll
        for (int i = 0; i < 2; i++) {
            int row = ldRow + i*64;
            cp16(bb + (uint32_t)((row*LDA + ldSeg*8)*2),
                 Bg + (size_t)row*Kc + k0 + ldSeg*8);
        }
    };

    load_tiles(0, 0);  cp_commit();
    load_tiles(1, 32); cp_commit();
    cp_wait1();
    __syncthreads();

    const int KT = Kc >> 5;
    for (int kt = 0; kt < KT; kt++) {
        int st = kt % 3;
        uint32_t ab = sb + (uint32_t)(st*STG*2);
        uint32_t bb = ab + (uint32_t)(ASZ*2);
        #pragma unroll
        for (int ks = 0; ks < 2; ks++) {
            uint32_t af[4][4], bfr[4][4];
            #pragma unroll
            for (int mt = 0; mt < 4; mt++)
                ldsm_x4(af[mt][0], af[mt][1], af[mt][2], af[mt][3],
                        ab + (uint32_t)(((aRow + mt*16)*LDA + aColH + ks*16) * 2));
            #pragma unroll
            for (int p = 0; p < 4; p++)
                ldsm_x4(bfr[p][0], bfr[p][1], bfr[p][2], bfr[p][3],
                        bb + (uint32_t)(((bRow + p*16)*LDA + bColH + ks*16) * 2));
            #pragma unroll
            for (int mt = 0; mt < 4; mt++)
                #pragma unroll
                for (int nt = 0; nt < 8; nt++)
                    mma16816(acc[mt][nt], af[mt], &bfr[nt >> 1][(nt & 1) * 2]);
        }
        if (kt + 2 < KT) load_tiles((kt + 2) % 3, (kt + 2) << 5);
        cp_commit();                 // empty group at tail keeps accounting right
        cp_wait1();                  // ensure tile kt+1 resident
        __syncthreads();
    }

    // ---------------- epilogue: registers -> global ----------------
    const int mbase = blockIdx.y*BM + warpM*64 + (lane >> 2);
    #pragma unroll
    for (int nt = 0; nt < 8; nt++) {
        int coll = warpN*64 + nt*8 + (lane & 3)*2;
        if (NSTORE < BN && coll >= NSTORE) continue;
        int gcol = blockIdx.x*BN + coll;
        float bx = 0.f, by = 0.f;
        if (BIAS) { bx = __ldg(&bias[gcol]); by = __ldg(&bias[gcol + 1]); }
        #pragma unroll
        for (int mt = 0; mt < 4; mt++) {
            float2 v0 = make_float2(acc[mt][nt][0] + bx, acc[mt][nt][1] + by);
            float2 v1 = make_float2(acc[mt][nt][2] + bx, acc[mt][nt][3] + by);
            if (RELU) {
                v0.x = fmaxf(v0.x, 0.f); v0.y = fmaxf(v0.y, 0.f);
                v1.x = fmaxf(v1.x, 0.f); v1.y = fmaxf(v1.y, 0.f);
            }
            size_t r0 = (size_t)(mbase + mt*16);
            *(float2*)&C[r0*ldc + gcol]       = v0;
            *(float2*)&C[(r0 + 8)*ldc + gcol] = v1;
        }
    }
}
#define GEMM_SMEM ((256*40 + 128*40) * 2 * 3)   // 92160 B

// ---------------- depthwise causal conv(4) + SiLU (+ hi/lo cat) -------------
__global__ void conv_silu_kernel(const float* __restrict__ cw, const float* __restrict__ cb,
                                 __nv_bfloat16* __restrict__ ucat) {
    int m = blockIdx.x;
    int d = threadIdx.x;
    int l = m & (SEQ - 1);
    float4 w4 = ((const float4*)cw)[d];
    const float* xc = g_XZ + (size_t)m * (2*DI) + d;
    float acc = cb[d] + w4.w * xc[0];
    if (l >= 1) acc += w4.z * xc[-(2*DI)];
    if (l >= 2) acc += w4.y * xc[-2*(2*DI)];
    if (l >= 3) acc += w4.x * xc[-3*(2*DI)];
    float u = acc * (1.0f / (1.0f + __expf(-acc)));
    g_U[(size_t)m*DI + d] = u;
    unsigned short h, lo;
    split_bf(u, h, lo);
    __nv_bfloat16* oc = ucat + (size_t)m*768 + d;
    oc[0]   = __ushort_as_bfloat16(h);
    oc[256] = __ushort_as_bfloat16(lo);
    oc[512] = __ushort_as_bfloat16(h);
}

// ---------------- dt = softplus(DBC[:, :8] @ Wdt[8,256] + b_dt) -------------
__global__ __launch_bounds__(256) void dt_kernel(const float* __restrict__ Wdt,
                                                 const float* __restrict__ bdt) {
    __shared__ float Ws[DR*DI];
    for (int i = threadIdx.x; i < DR*DI; i += 256) Ws[i] = Wdt[i];
    __syncthreads();
    int d  = threadIdx.x;
    float bv = bdt[d];
    int m0 = blockIdx.x * 16;
    for (int p = 0; p < 16; p++) {
        int m = m0 + p;
        const float* r = g_DBC + (size_t)m * DXPP;
        float acc = bv;
        #pragma unroll
        for (int j = 0; j < DR; j++) acc += r[j] * Ws[j*DI + d];
        g_DT[(size_t)m*DI + d] = (acc > 20.f) ? acc : log1pf(__expf(acc));
    }
}

// -------- tiled transpose: dt/u/z token-major -> channel-major [b*DI+d][L] --
__global__ void trans_kernel() {
    __shared__ float t0[32][33];
    __shared__ float t1[32][33];
    __shared__ float t2[32][33];
    int l0 = blockIdx.x * 32, d0 = blockIdx.y * 32, b = blockIdx.z;
    int tx = threadIdx.x, ty = threadIdx.y;
    #pragma unroll
    for (int i = ty; i < 32; i += 8) {
        size_t m = (size_t)b*SEQ + l0 + i;
        t0[i][tx] = g_DT[m*DI + d0 + tx];
        t1[i][tx] = g_U [m*DI + d0 + tx];
        t2[i][tx] = g_XZ[m*2*DI + DI + d0 + tx];
    }
    __syncthreads();
    #pragma unroll
    for (int i = ty; i < 32; i += 8) {
        size_t ch = (size_t)b*DI + d0 + i;
        g_DTt[ch*SEQ + l0 + tx] = t0[tx][i];
        g_Ut [ch*SEQ + l0 + tx] = t1[tx][i];
        g_Zt [ch*SEQ + l0 + tx] = t2[tx][i];
    }
}

// ---------------- selective scan: smem-staged, cp.async double-buffered -----
__global__ __launch_bounds__(256) void scan_kernel(const float* __restrict__ A_log,
                                                   const float* __restrict__ D_skip,
                                                   __nv_bfloat16* __restrict__ ycat) {
    __shared__ __align__(16) float dts[2][16][TSS];
    __shared__ __align__(16) float us [2][16][TSS];
    __shared__ __align__(16) float zs [2][16][TSS];
    __shared__ __align__(16) float bcs[2][TSS][32];
    const int tid = threadIdx.x, warp = tid >> 5, lane = tid & 31;
    const int half = lane >> 4, s = lane & 15;
    const int b  = blockIdx.x >> 4;
    const int dg = (blockIdx.x & 15) << 4;
    const int chl = warp*2 + half;
    const int d = dg + chl;
    const float a   = -__expf(A_log[d*DS + s]);
    const float dsk = D_skip[d];
    const float* dtp = g_DTt + ((size_t)b*DI + dg)*SEQ;
    const float* up  = g_Ut  + ((size_t)b*DI + dg)*SEQ;
    const float* zp  = g_Zt  + ((size_t)b*DI + dg)*SEQ;
    const float* bcp = g_DBC + (size_t)b*SEQ*DXPP;

    const int lrow = tid >> 4, lseg = tid & 15;

    auto load_tile = [&](int buf, int l0) {
        size_t goff = (size_t)lrow*SEQ + l0 + lseg*4;
        cp16(smem_u32(&dts[buf][lrow][lseg*4]), dtp + goff);
        cp16(smem_u32(&us [buf][lrow][lseg*4]), up  + goff);
        cp16(smem_u32(&zs [buf][lrow][lseg*4]), zp  + goff);
        #pragma unroll
        for (int r = 0; r < 2; r++) {
            int idx = tid + r*256;
            int j = idx >> 3, seg = idx & 7;
            cp16(smem_u32(&bcs[buf][j][seg*4]),
                 bcp + (size_t)(l0 + j)*DXPP + DR + seg*4);
        }
        cp_commit();
    };

    load_tile(0, 0);
    float h = 0.f;
    const int NT = SEQ / TSS;
    for (int t = 0; t < NT; t++) {
        int buf = t & 1;
        cp_wait0();
        __syncthreads();
        if (t + 1 < NT) load_tile(buf ^ 1, (t + 1) * TSS);
        #pragma unroll 4
        for (int j = 0; j < TSS; j++) {
            float dtv = dts[buf][chl][j];
            float uv  = us [buf][chl][j];
            float Bv  = bcs[buf][j][s];
            float Cv  = bcs[buf][j][16 + s];
            h = __expf(dtv * a) * h + dtv * uv * Bv;
            float y = h * Cv;
            y += __shfl_xor_sync(0xffffffffu, y, 8);
            y += __shfl_xor_sync(0xffffffffu, y, 4);
            y += __shfl_xor_sync(0xffffffffu, y, 2);
            y += __shfl_xor_sync(0xffffffffu, y, 1);
            if (s == 0) {
                float zv  = zs[buf][chl][j];
                float val = (y + uv * dsk) * (zv / (1.0f + __expf(-zv)));
                unsigned short hh, ll;
                split_bf(val, hh, ll);
                size_t m = (size_t)b*SEQ + t*TSS + j;
                __nv_bfloat16* oc = ycat + m*768 + d;
                oc[0]   = __ushort_as_bfloat16(hh);
                oc[256] = __ushort_as_bfloat16(ll);
                oc[512] = __ushort_as_bfloat16(hh);
            }
        }
    }
}

// ---------------- host launch ----------------
extern "C" void kernel_launch(void* const* d_in, const int* in_sizes, int n_in,
                              void* d_out, int out_size) {
    const int*   tokens  = (const int*)  d_in[0];
    const float* emb     = (const float*)d_in[1];
    const float* ln_w    = (const float*)d_in[2];
    const float* ln_b    = (const float*)d_in[3];
    const float* W_in    = (const float*)d_in[4];
    const float* conv_w  = (const float*)d_in[5];
    const float* conv_b  = (const float*)d_in[6];
    const float* W_xproj = (const float*)d_in[7];
    const float* W_dt    = (const float*)d_in[8];
    const float* b_dt    = (const float*)d_in[9];
    const float* A_log   = (const float*)d_in[10];
    const float* D_skip  = (const float*)d_in[11];
    const float* W_out   = (const float*)d_in[12];
    const float* W1      = (const float*)d_in[13];
    const float* b1      = (const float*)d_in[14];
    const float* W2      = (const float*)d_in[15];
    const float* b2      = (const float*)d_in[16];
    float* out = (float*)d_out;

    cudaFuncSetAttribute(mma_gemm_kernel<128,false,false>,
                         cudaFuncAttributeMaxDynamicSharedMemorySize, GEMM_SMEM);
    cudaFuncSetAttribute(mma_gemm_kernel<64,false,false>,
                         cudaFuncAttributeMaxDynamicSharedMemorySize, GEMM_SMEM);
    cudaFuncSetAttribute(mma_gemm_kernel<128,true,true>,
                         cudaFuncAttributeMaxDynamicSharedMemorySize, GEMM_SMEM);
    cudaFuncSetAttribute(mma_gemm_kernel<128,true,false>,
                         cudaFuncAttributeMaxDynamicSharedMemorySize, GEMM_SMEM);

    float *X, *XZ, *DBC, *H;
    __nv_bfloat16 *Acat, *Bcat;
    cudaGetSymbolAddress((void**)&X,    g_X);
    cudaGetSymbolAddress((void**)&XZ,   g_XZ);
    cudaGetSymbolAddress((void**)&DBC,  g_DBC);
    cudaGetSymbolAddress((void**)&H,    g_H);
    cudaGetSymbolAddress((void**)&Acat, g_Acat);
    cudaGetSymbolAddress((void**)&Bcat, g_Bcat);

    embed_kernel<<<MTOT*32/256, 256>>>(tokens, emb);

    for (int layer = 0; layer < NL; layer++) {
        // LN + split-bf16 cat (Kc = 3*128 = 384)
        ln_cvt_kernel<<<MTOT/8, 256>>>(ln_w + layer*DM, ln_b + layer*DM, X, Acat);
        // xz = xn @ W_in : [32768,128]x[128,512]
        cvtB_kernel<<<dim3(DM/32, 2*DI/32), dim3(32,8)>>>(
            W_in + (size_t)layer*DM*2*DI, Bcat, DM, 2*DI, 2*DI);
        mma_gemm_kernel<128,false,false><<<dim3(4, 128), 256, GEMM_SMEM>>>(
            384, Acat, Bcat, nullptr, XZ, 2*DI);
        // conv + silu (+ cat for xproj, Kc = 3*256 = 768)
        conv_silu_kernel<<<MTOT, DI>>>(conv_w + (size_t)layer*DI*4,
                                       conv_b + (size_t)layer*DI, Acat);
        // dbc = u @ W_xproj : [32768,256]x[256,40], B padded to 128 rows
        cvtB_kernel<<<dim3(DI/32, 128/32), dim3(32,8)>>>(
            W_xproj + (size_t)layer*DI*40, Bcat, DI, 40, 128);
        mma_gemm_kernel<64,false,false><<<dim3(1, 128), 256, GEMM_SMEM>>>(
            768, Acat, Bcat, nullptr, DBC, DXPP);
        // dt
        dt_kernel<<<MTOT/16, 256>>>(W_dt + (size_t)layer*DR*DI, b_dt + (size_t)layer*DI);
        // transpose dt/u/z to channel-major for the scan
        trans_kernel<<<dim3(SEQ/32, DI/32, BATCH), dim3(32, 8)>>>();
        // selective scan + gating (+ cat for W_out)
        scan_kernel<<<BATCH*DI/16, 256>>>(A_log  + (size_t)layer*DI*DS,
                                          D_skip + (size_t)layer*DI, Acat);
        // x = y @ W_out : [32768,256]x[256,128]
        cvtB_kernel<<<dim3(DI/32, DM/32), dim3(32,8)>>>(
            W_out + (size_t)layer*DI*DM, Bcat, DI, DM, DM);
        mma_gemm_kernel<128,false,false><<<dim3(1, 128), 256, GEMM_SMEM>>>(
            768, Acat, Bcat, nullptr, X, DM);
    }

    // h = relu(x @ W1 + b1) : [32768,128]x[128,512]
    cvtA_kernel<<<MTOT*DM/4/256, 256>>>(X, Acat, DM);
    cvtB_kernel<<<dim3(DM/32, DFF/32), dim3(32,8)>>>(W1, Bcat, DM, DFF, DFF);
    mma_gemm_kernel<128,true,true><<<dim3(4, 128), 256, GEMM_SMEM>>>(
        384, Acat, Bcat, b1, H, DFF);
    // out = h @ W2 + b2 : [32768,512]x[512,4096]
    cvtA_kernel<<<MTOT*DFF/4/256, 256>>>(H, Acat, DFF);
    cvtB_kernel<<<dim3(DFF/32, VOCABSZ/32), dim3(32,8)>>>(W2, Bcat, DFF, VOCABSZ, VOCABSZ);
    mma_gemm_kernel<128,true,false><<<dim3(VOCABSZ/128, 128), 256, GEMM_SMEM>>>(
        1536, Acat, Bcat, b2, out, VOCABSZ);
}